// round 5
// baseline (speedup 1.0000x reference)
#include <cuda_runtime.h>
#include <cstdint>

// Conv2d 3x3 s1 p1 NCHW fp32: N=32,C=128,H=W=56,OC=256.
// Implicit GEMM, mma.sync.m16n8k8.tf32, K reordered as k' = tap*128 + c.
// Prep kernels pre-convert input & weights to TF32 (weights in fragment order).
// R5: single __syncthreads per stage; loads issued before MMA burst.

#define N_IMG   32
#define C_IN    128
#define H_DIM   56
#define W_DIM   56
#define OC_DIM  256
#define HW      3136
#define K_TOTAL 1152
#define M_TOTAL 100352

#define BM 128
#define BN 128
#define BK 32
#define THREADS 256
#define NSTAGES 36                      // K_TOTAL / BK

#define STAGE_BYTES 32768               // A 16KB + B 16KB (fragment order)
#define SMEM_TOTAL  (3 * STAGE_BYTES)   // 96KB, 3-stage ring

__device__ __align__(16) float    g_in_t[N_IMG * C_IN * HW];   // tf32 input copy
__device__ __align__(16) uint32_t g_w_t[OC_DIM * K_TOTAL];     // tf32 frag weights

__device__ __forceinline__ uint32_t smem_u32(const void* p) {
    uint32_t a;
    asm("{ .reg .u64 t; cvta.to.shared.u64 t, %1; cvt.u32.u64 %0, t; }" : "=r"(a) : "l"(p));
    return a;
}
__device__ __forceinline__ uint32_t f2tf32(float f) {
    uint32_t u;
    asm("cvt.rna.tf32.f32 %0, %1;" : "=r"(u) : "f"(f));
    return u;
}
__device__ __forceinline__ void cp4_zfill(uint32_t dst, const void* src, uint32_t sz) {
    asm volatile("cp.async.ca.shared.global [%0], [%1], 4, %2;"
                 :: "r"(dst), "l"(src), "r"(sz) : "memory");
}
__device__ __forceinline__ void cp16(uint32_t dst, const void* src) {
    asm volatile("cp.async.cg.shared.global [%0], [%1], 16;"
                 :: "r"(dst), "l"(src) : "memory");
}
__device__ __forceinline__ void lds128(uint32_t* r, uint32_t addr) {
    asm volatile("ld.shared.v4.u32 {%0,%1,%2,%3}, [%4];"
                 : "=r"(r[0]), "=r"(r[1]), "=r"(r[2]), "=r"(r[3]) : "r"(addr));
}
__device__ __forceinline__ void mma_tf32(float* c,
                                         const uint32_t* a, uint32_t b0, uint32_t b1) {
    asm volatile(
        "mma.sync.aligned.m16n8k8.row.col.f32.tf32.tf32.f32 "
        "{%0,%1,%2,%3}, {%4,%5,%6,%7}, {%8,%9}, {%0,%1,%2,%3};"
        : "+f"(c[0]), "+f"(c[1]), "+f"(c[2]), "+f"(c[3])
        : "r"(a[0]), "r"(a[1]), "r"(a[2]), "r"(a[3]), "r"(b0), "r"(b1));
}

// ---- prep: input -> tf32 bits, same layout ----
__global__ void prep_in_kernel(const float* __restrict__ in) {
    const int i = blockIdx.x * blockDim.x + threadIdx.x;   // float4 index
    float4 v = ((const float4*)in)[i];
    float4 o;
    o.x = __uint_as_float(f2tf32(v.x));
    o.y = __uint_as_float(f2tf32(v.y));
    o.z = __uint_as_float(f2tf32(v.z));
    o.w = __uint_as_float(f2tf32(v.w));
    ((float4*)g_in_t)[i] = o;
}

// ---- prep: weights -> tf32, fragment order keyed by k' = rs*128 + c ----
__global__ void prep_w_kernel(const float* __restrict__ w) {
    const int idx = blockIdx.x * blockDim.x + threadIdx.x;  // oc*1152 + c*9 + rs
    const int oc = idx / K_TOTAL;
    const int kf = idx - oc * K_TOTAL;
    const int c  = kf / 9;
    const int rs = kf - c * 9;
    const int kp = rs * 128 + c;             // reordered K
    const int s   = kp >> 5;
    const int kl  = kp & 31;
    const int ks  = kl >> 3;
    const int tig = kl & 3;
    const int kh  = (kl >> 2) & 1;
    const int nh  = oc >> 7;
    const int ocl = oc & 127;
    const int tp  = ocl >> 4;
    const int tpo = (ocl >> 3) & 1;
    const int grp = ocl & 7;
    const int word = ((s * 2 + nh) * 4 + ks) * 1024
                   + tp * 128 + grp * 16 + tig * 4 + tpo * 2 + kh;
    g_w_t[word] = f2tf32(w[idx]);
}

__global__ void __launch_bounds__(THREADS, 2)
conv2d_mma_kernel(const float* __restrict__ bias, float* __restrict__ out)
{
    extern __shared__ char smem_raw[];
    const uint32_t sbase = smem_u32(smem_raw);

    const int tid     = threadIdx.x;
    const int lane    = tid & 31;
    const int wid     = tid >> 5;
    const int m_base  = blockIdx.x * BM;
    const int nhalf   = blockIdx.y;            // oc half (0 / 1)
    const int oc_base = nhalf * BN;

    // ---- A gather mapping ----
    const int a_m    = tid & 127;
    const int a_kq   = (tid >> 7) * 16;        // k_local base: 0 or 16
    const int tile_m = a_m >> 4;
    const int grp_w  = a_m & 7;
    const int half_w = (a_m >> 3) & 1;
    const int m_g    = m_base + a_m;
    const int n_img  = m_g / HW;
    const int hw     = m_g - n_img * HW;
    const int h      = hw / W_DIM;
    const int w      = hw - h * W_DIM;
    const float* in_t_n = g_in_t + (size_t)n_img * (C_IN * HW) + hw;

    // stage-invariant A dst base (word units); per-j delta is compile-time const
    const uint32_t a_dst0 = (uint32_t)((a_kq >> 3) * 1024 + tile_m * 128
                                       + grp_w * 4 + half_w);

    // ---- loader state (stage lt, tap = lt>>2) ----
    int lt = 0, lr = 0, lsq = 0;
    auto load_next = [&]() {
        const uint32_t abase = sbase + (lt % 3) * STAGE_BYTES;
        const uint32_t bbase = abase + 16384;
        const bool ok = ((unsigned)(h + lr - 1) < (unsigned)H_DIM) &&
                        ((unsigned)(w + lsq - 1) < (unsigned)W_DIM);
        const uint32_t sz = ok ? 4u : 0u;
        const float* p = in_t_n + (lr - 1) * W_DIM + (lsq - 1)
                       + (size_t)((lt & 3) * 32 + a_kq) * HW;
        const uint32_t adst = abase + a_dst0 * 4;
        #pragma unroll
        for (int j = 0; j < 16; j++) {
            const uint32_t dj = (uint32_t)((j >> 3) * 1024 + (j & 3) * 32
                               + ((j >> 2) & 1) * 2) * 4;
            cp4_zfill(adst + dj, p + (size_t)j * HW, sz);
        }
        const uint32_t* wsrc = g_w_t + (size_t)(lt * 2 + nhalf) * 4096;
        #pragma unroll
        for (int j = 0; j < 4; j++) {
            const int cchunk = tid + 256 * j;
            cp16(bbase + cchunk * 16, wsrc + cchunk * 4);
        }
        asm volatile("cp.async.commit_group;" ::: "memory");
        lt++;
        if ((lt & 3) == 0) { lsq++; if (lsq == 3) { lsq = 0; lr++; } }
    };

    // ---- compute mapping: 4(M) x 2(N) warps, warp tile 32x64 ----
    const int wm  = wid & 3;
    const int wn  = wid >> 2;
    const int grp = lane >> 2;
    const int tig = lane & 3;
    const uint32_t a_roff = (uint32_t)((tig * 8 + grp) * 16);   // bytes
    const uint32_t b_roff = (uint32_t)(grp * 64 + tig * 16);    // bytes

    float acc[2][8][4];
    #pragma unroll
    for (int mi = 0; mi < 2; mi++)
        #pragma unroll
        for (int ni = 0; ni < 8; ni++)
            #pragma unroll
            for (int q = 0; q < 4; q++) acc[mi][ni][q] = 0.0f;

    load_next();            // stage 0 -> buf 0
    load_next();            // stage 1 -> buf 1

    int buf = 0;
    for (int s = 0; s < NSTAGES; s++) {
        if (s == NSTAGES - 1)
            asm volatile("cp.async.wait_group 0;" ::: "memory");
        else
            asm volatile("cp.async.wait_group 1;" ::: "memory");
        __syncthreads();
        // buffer (s+2)%3 == (s-1)%3 was consumed at stage s-1; safe to refill now
        if (s + 2 < NSTAGES) load_next();

        const uint32_t Ab = sbase + buf * STAGE_BYTES;
        const uint32_t Bb = Ab + 16384;
        #pragma unroll
        for (int ks = 0; ks < 4; ks++) {
            uint32_t a[2][4];
            #pragma unroll
            for (int mi = 0; mi < 2; mi++)
                lds128(a[mi], Ab + (uint32_t)((ks * 8 + wm * 2 + mi) * 512) + a_roff);
            uint32_t bb[4][4];
            #pragma unroll
            for (int t = 0; t < 4; t++)
                lds128(bb[t], Bb + (uint32_t)((ks * 8 + wn * 4 + t) * 512) + b_roff);
            #pragma unroll
            for (int t = 0; t < 4; t++)
                #pragma unroll
                for (int tpo = 0; tpo < 2; tpo++) {
                    const int ni = t * 2 + tpo;
                    #pragma unroll
                    for (int mi = 0; mi < 2; mi++)
                        mma_tf32(acc[mi][ni], a[mi], bb[t][tpo * 2], bb[t][tpo * 2 + 1]);
                }
        }
        buf = (buf == 2) ? 0 : buf + 1;
    }

    // ---- epilogue: +bias (fp32), scatter to NCHW ----
    #pragma unroll
    for (int mi = 0; mi < 2; mi++) {
        const int row0 = m_base + wm * 32 + mi * 16 + grp;
        #pragma unroll
        for (int hf = 0; hf < 2; hf++) {
            const int m   = row0 + 8 * hf;
            const int nn  = m / HW;
            const int phw = m - nn * HW;
            float* op = out + (size_t)nn * OC_DIM * HW + phw;
            #pragma unroll
            for (int ni = 0; ni < 8; ni++) {
                const int oc = oc_base + wn * 64 + ni * 8 + 2 * tig;
                const float b0 = __ldg(bias + oc);
                const float b1 = __ldg(bias + oc + 1);
                op[(size_t)oc * HW]       = acc[mi][ni][2 * hf + 0] + b0;
                op[(size_t)(oc + 1) * HW] = acc[mi][ni][2 * hf + 1] + b1;
            }
        }
    }
}

extern "C" void kernel_launch(void* const* d_in, const int* in_sizes, int n_in,
                              void* d_out, int out_size)
{
    const float* in   = (const float*)d_in[0];
    const float* wgt  = (const float*)d_in[1];
    const float* bias = (const float*)d_in[2];
    float* out        = (float*)d_out;

    prep_in_kernel<<<(N_IMG * C_IN * HW / 4) / 256, 256>>>(in);
    prep_w_kernel<<<(OC_DIM * K_TOTAL) / 256, 256>>>(wgt);

    cudaFuncSetAttribute(conv2d_mma_kernel,
                         cudaFuncAttributeMaxDynamicSharedMemorySize, SMEM_TOTAL);
    dim3 grid(M_TOTAL / BM, OC_DIM / BN, 1);   // 784 x 2
    conv2d_mma_kernel<<<grid, THREADS, SMEM_TOTAL>>>(bias, out);
}